// round 15
// baseline (speedup 1.0000x reference)
#include <cuda_runtime.h>
#include <math.h>

#define Bn 4
#define Tn 2048
#define Dn 1024
#define Hn 16
#define HDn 64
#define En 16
#define Rn 64                     // Bn*En active rows
#define QK_SCALE 0.35355339059327373f   // hd^-0.25
#define SM_SCALE 0.125f                 // 1/sqrt(hd)

typedef unsigned long long u64;

// ---------------- scratch (static device globals; no allocation) ----------
__device__ float g_xn[Rn * Dn];
__device__ float g_q[Rn * Dn];     // q init (post-bias/scale), flat [1024][64]
__device__ float g_k[Rn * Dn];     // k init
__device__ float g_v[Rn * Dn];     // v init
__device__ float g_ks[3 * 65536];  // LN'd kl per iteration
__device__ float g_vl[3 * 65536];  // vl per iteration
__device__ float g_ai1[Rn * Dn];
__device__ float g_ai2[Rn * Dn];
__device__ float g_Wp[6][4096];    // W^1..3 for k (0..2) and v (3..5)
__device__ float g_bp[6][64];      // composite biases
__device__ float g_diffsum;

// ---------------- helpers -------------------------------------------------
__device__ __forceinline__ float warpReduceSum(float v) {
#pragma unroll
    for (int o = 16; o > 0; o >>= 1) v += __shfl_xor_sync(0xffffffffu, v, o);
    return v;
}

__device__ __forceinline__ float blockReduce256(float v, float* sh) {
    __syncthreads();
    v = warpReduceSum(v);
    int wid = threadIdx.x >> 5;
    if ((threadIdx.x & 31) == 0) sh[wid] = v;
    __syncthreads();
    if (threadIdx.x < 32) {
        float t = (threadIdx.x < 8) ? sh[threadIdx.x] : 0.f;
        t = warpReduceSum(t);
        if (threadIdx.x == 0) sh[0] = t;
    }
    __syncthreads();
    return sh[0];
}

// packed fp32x2 FMA (sm_100+)
__device__ __forceinline__ void ffma2(u64& d, u64 a, u64 b) {
    asm("fma.rn.f32x2 %0, %1, %2, %0;" : "+l"(d) : "l"(a), "l"(b));
}
__device__ __forceinline__ u64 fadd2(u64 a, u64 b) {
    u64 r;
    asm("add.rn.f32x2 %0, %1, %2;" : "=l"(r) : "l"(a), "l"(b));
    return r;
}
__device__ __forceinline__ u64 pack2(float a, float b) {
    u64 r;
    asm("mov.b64 %0, {%1, %2};" : "=l"(r) : "f"(a), "f"(b));
    return r;
}
__device__ __forceinline__ float lo32(u64 v) { return ((float2*)&v)->x; }
__device__ __forceinline__ float hi32(u64 v) { return ((float2*)&v)->y; }

__device__ __forceinline__ unsigned smem_u32p(const void* p) {
    return (unsigned)__cvta_generic_to_shared(p);
}
__device__ __forceinline__ void cp16(unsigned dst, const void* src) {
    asm volatile("cp.async.cg.shared.global [%0], [%1], 16;" :: "r"(dst), "l"(src));
}
__device__ __forceinline__ void cp8(unsigned dst, const void* src) {
    asm volatile("cp.async.ca.shared.global [%0], [%1], 8;" :: "r"(dst), "l"(src));
}
__device__ __forceinline__ void cp_commit() {
    asm volatile("cp.async.commit_group;");
}
__device__ __forceinline__ void cp_wait0() {
    asm volatile("cp.async.wait_group 0;");
}
// vector float atomic add (sm_90+)
__device__ __forceinline__ void red4(float* p, float a, float b, float c, float d) {
    asm volatile("red.global.add.v4.f32 [%0], {%1,%2,%3,%4};"
                 :: "l"(p), "f"(a), "f"(b), "f"(c), "f"(d) : "memory");
}

// full-warp LN over 64 elements held as one f32x2 pair per lane
__device__ __forceinline__ u64 ln_pair(u64 y, u64 gamma, float scale) {
    float a = lo32(y), b = hi32(y);
    float s = a + b;
#pragma unroll
    for (int o = 16; o > 0; o >>= 1) s += __shfl_xor_sync(0xffffffffu, s, o);
    float mean = s * (1.f / 64.f);
    float da = a - mean, db = b - mean;
    float q = da * da + db * db;
#pragma unroll
    for (int o = 16; o > 0; o >>= 1) q += __shfl_xor_sync(0xffffffffu, q, o);
    float inv = rsqrtf(q * (1.f / 64.f) + 1e-5f) * scale;
    return pack2(da * inv * lo32(gamma), db * inv * hi32(gamma));
}

// ======================= K1a: LN(64 rows) + accumulator inits =============
__global__ __launch_bounds__(256) void k_ln(
    const float* __restrict__ x, const float* __restrict__ lna,
    const float* __restrict__ bq, const float* __restrict__ bv) {
    if (blockIdx.x < Rn) {
        __shared__ float sh[8];
        if (blockIdx.x == 0 && threadIdx.x == 0) g_diffsum = 0.f;
        int r = blockIdx.x;
        int b = r >> 4, t = r & 15;
        const float* xr = x + ((size_t)(b * Tn + t)) * Dn;
        int tid = threadIdx.x;
        float v[4];
        float s = 0.f;
#pragma unroll
        for (int i = 0; i < 4; i++) { v[i] = xr[tid + i * 256]; s += v[i]; }
        s = blockReduce256(s, sh);
        float mean = s * (1.f / 1024.f);
        float sq = 0.f;
#pragma unroll
        for (int i = 0; i < 4; i++) { float d = v[i] - mean; sq += d * d; }
        sq = blockReduce256(sq, sh);
        float inv = rsqrtf(sq * (1.f / 1024.f) + 1e-5f);
#pragma unroll
        for (int i = 0; i < 4; i++) {
            int j = tid + i * 256;
            g_xn[r * Dn + j] = (v[i] - mean) * inv * lna[j];
        }
    } else {
        int r = blockIdx.x - Rn;
        int tid = threadIdx.x;
#pragma unroll
        for (int i = 0; i < 4; i++) {
            int j = tid + i * 256;
            g_q[r * Dn + j] = bq[j] * QK_SCALE;
            g_k[r * Dn + j] = 0.f;
            g_v[r * Dn + j] = bv[j];
        }
    }
}

// ======================= K1b: bo fill of whole output (side stream) =======
__global__ __launch_bounds__(256) void k_fill(
    const float* __restrict__ bo, float* __restrict__ out) {
    const float4* bo4 = (const float4*)bo;
    float4* o4 = (float4*)out;
    size_t total = (size_t)Bn * Tn * Dn / 4;
    size_t start = (size_t)blockIdx.x * 256 + threadIdx.x;
    size_t stride = (size_t)gridDim.x * 256;
    float4 v = bo4[start & 255];
    for (size_t i = start; i < total; i += stride) o4[i] = v;
}

// ======================= K1c: weight powers + composite biases ============
// 2 blocks (0=K, 1=V). Computes W, W^2, W^3 and biases b, Wb+b, W(Wb+b)+b.
// Runs on the side stream, hidden behind k_ln/k_qkv (depends only on weights).
__global__ __launch_bounds__(256) void k_pow(
    const float* __restrict__ Wlk, const float* __restrict__ blk,
    const float* __restrict__ Wlv, const float* __restrict__ blv) {
    __shared__ float sW[4096];
    __shared__ float sW2[4096];
    __shared__ float sb[64], sc1[64];
    int m = blockIdx.x;
    int base = m * 3;
    const float* W = m ? Wlv : Wlk;
    const float* b = m ? blv : blk;
    int tid = threadIdx.x;
    for (int i = tid; i < 4096; i += 256) {
        float v = W[i];
        sW[i] = v;
        g_Wp[base][i] = v;
    }
    if (tid < 64) {
        float v = b[tid];
        sb[tid] = v;
        g_bp[base][tid] = v;
    }
    __syncthreads();
    int j = tid >> 2, d0 = (tid & 3) * 16;
    // W2 = W @ W
    float acc[16] = {};
    for (int k = 0; k < 64; k++) {
        float wjk = sW[j * 64 + k];
#pragma unroll
        for (int dd = 0; dd < 16; dd++)
            acc[dd] = fmaf(wjk, sW[k * 64 + d0 + dd], acc[dd]);
    }
#pragma unroll
    for (int dd = 0; dd < 16; dd++) {
        sW2[j * 64 + d0 + dd] = acc[dd];
        g_Wp[base + 1][j * 64 + d0 + dd] = acc[dd];
    }
    if (tid < 64) {                 // c1 = W b + b
        float s = sb[tid];
        for (int k = 0; k < 64; k++) s = fmaf(sW[tid * 64 + k], sb[k], s);
        sc1[tid] = s;
        g_bp[base + 1][tid] = s;
    }
    __syncthreads();
    // W3 = W2 @ W
    float acc3[16] = {};
    for (int k = 0; k < 64; k++) {
        float w2jk = sW2[j * 64 + k];
#pragma unroll
        for (int dd = 0; dd < 16; dd++)
            acc3[dd] = fmaf(w2jk, sW[k * 64 + d0 + dd], acc3[dd]);
    }
#pragma unroll
    for (int dd = 0; dd < 16; dd++)
        g_Wp[base + 2][j * 64 + d0 + dd] = acc3[dd];
    if (tid < 64) {                 // c2 = W c1 + b
        float s = sb[tid];
        for (int k = 0; k < 64; k++) s = fmaf(sW[tid * 64 + k], sc1[k], s);
        g_bp[base + 2][tid] = s;
    }
}

// ======================= 64x128 FFMA2 GEMM tile core ======================
#define TK 64

__device__ __forceinline__ void stage_tile(
    const float* __restrict__ A, const float* __restrict__ W,
    int j0, int kb, float* sA, float* sW) {
    int tid = threadIdx.x;
#pragma unroll
    for (int c = tid; c < 64 * TK / 2; c += 128) {
        int r = c >> 5;
        int kf = (c & 31) * 2;
        int rg = r >> 3;
        int swz = ((rg & 3) * 8) | ((rg >> 2) * 2);
        cp8(smem_u32p(&sA[r * TK + (kf ^ swz)]),
            &A[(size_t)r * Dn + kb + kf]);
    }
#pragma unroll
    for (int c = tid; c < 128 * TK / 4; c += 128) {
        int r = c >> 4;
        int kf = (c & 15) * 4;
        cp16(smem_u32p(&sW[r * TK + kf]),
             &W[(size_t)(j0 + r) * Dn + kb + kf]);
    }
    cp_commit();
}

__device__ __forceinline__ void compute_tile(
    const float* sA, const float* sW, u64* acc, int rg, int cg) {
    int swz = ((rg & 3) * 8) | ((rg >> 2) * 2);
    const float* aBase = sA + rg * 8 * TK;
    const float* wBase = sW + cg * 8 * TK;
#pragma unroll 4
    for (int kk = 0; kk < TK; kk += 2) {
        int ka = kk ^ swz;
        u64 av[8], wv[8];
#pragma unroll
        for (int i = 0; i < 8; i++)
            av[i] = *(const u64*)&aBase[i * TK + ka];
#pragma unroll
        for (int j = 0; j < 8; j++)
            wv[j] = *(const u64*)&wBase[j * TK + kk];
#pragma unroll
        for (int i = 0; i < 8; i++)
#pragma unroll
            for (int j = 0; j < 8; j++) ffma2(acc[i * 8 + j], av[i], wv[j]);
    }
}
#define GEMM_SMEM ((64 + 128) * TK * 4)   // 49152 bytes

// ======================= K2: q,k,v GEMMs (k-split 16, red.v4) =============
__global__ __launch_bounds__(128) void k_qkv(
    const float* __restrict__ Wq, const float* __restrict__ Wk,
    const float* __restrict__ Wv) {
    extern __shared__ float sh[];
    float* sA = sh;
    float* sW = sh + 64 * TK;
    int m = blockIdx.z;
    const float* W = (m == 0) ? Wq : (m == 1) ? Wk : Wv;
    float* dst = (m == 0) ? g_q : (m == 1) ? g_k : g_v;
    float scale = (m == 2) ? 1.0f : QK_SCALE;
    int j0 = blockIdx.x * 128;
    int kb = blockIdx.y * TK;
    u64 acc[64] = {};
    stage_tile(g_xn, W, j0, kb, sA, sW);
    cp_wait0();
    __syncthreads();
    int tid = threadIdx.x, rg = tid & 7, cg = tid >> 3;
    compute_tile(sA, sW, acc, rg, cg);
    int c0 = j0 + cg * 8;
#pragma unroll
    for (int i = 0; i < 8; i++) {
        int row = rg * 8 + i;
        float v[8];
#pragma unroll
        for (int j = 0; j < 8; j++) {
            float2 f = *(float2*)&acc[i * 8 + j];
            v[j] = (f.x + f.y) * scale;
        }
        float* p = &dst[(size_t)row * Dn + c0];
        red4(p, v[0], v[1], v[2], v[3]);
        red4(p + 4, v[4], v[5], v[6], v[7]);
    }
}

// ======================= K3a: flat k/v projections (all 3 iterations) =====
// kl_it = W^{it+1} k0 + c_it  (c precomputed) -> all 6 (it, mat) combos are
// independent. grid (32 row-tiles, 6): y<3 -> K power y; y>=3 -> V power y-3.
// Block: 32 rows, 8 warps x 4 rows. Weights staged transposed (conflict-free
// LDS.128); single pass, no recurrence, full unroll MLP.
__global__ __launch_bounds__(256, 1) void k_KV(const float* __restrict__ lnd) {
    __shared__ u64 wl[2048];          // wl[s*64+j]
    __shared__ u64 sx[32 * 33];
    int tid = threadIdx.x, lane = tid & 31, w = tid >> 5;
    int y = blockIdx.y;
    bool isK = (y < 3);
    int it = isK ? y : y - 3;
    int r0 = blockIdx.x * 32;
    const float* Wm = g_Wp[y];
    const float* src = isK ? g_k : g_v;
    for (int i = tid; i < 2048; i += 256) {
        int j = i >> 5, s = i & 31;
        cp8(smem_u32p(&wl[s * 64 + j]), &Wm[j * 64 + 2 * s]);
    }
    for (int i = tid; i < 1024; i += 256) {
        int r = i >> 5, s = i & 31;
        cp8(smem_u32p(&sx[r * 33 + s]), &src[(size_t)(r0 + r) * 64 + 2 * s]);
    }
    cp_commit();
    u64 bl_p = *(const u64*)&g_bp[y][2 * lane];
    u64 lnd_p = *(const u64*)&lnd[2 * lane];
    cp_wait0();
    __syncthreads();
    int xr0 = w * 4;

    u64 acc[4][2] = {};
#pragma unroll 8
    for (int s = 0; s < 32; s++) {
        ulonglong2 wv = *(const ulonglong2*)&wl[s * 64 + 2 * lane];
        u64 x0 = sx[(xr0 + 0) * 33 + s];
        u64 x1 = sx[(xr0 + 1) * 33 + s];
        u64 x2 = sx[(xr0 + 2) * 33 + s];
        u64 x3 = sx[(xr0 + 3) * 33 + s];
        ffma2(acc[0][0], x0, wv.x); ffma2(acc[0][1], x0, wv.y);
        ffma2(acc[1][0], x1, wv.x); ffma2(acc[1][1], x1, wv.y);
        ffma2(acc[2][0], x2, wv.x); ffma2(acc[2][1], x2, wv.y);
        ffma2(acc[3][0], x3, wv.x); ffma2(acc[3][1], x3, wv.y);
    }
#pragma unroll
    for (int rr = 0; rr < 4; rr++) {
        u64 pair = pack2(lo32(acc[rr][0]) + hi32(acc[rr][0]) + lo32(bl_p),
                         lo32(acc[rr][1]) + hi32(acc[rr][1]) + hi32(bl_p));
        size_t g = (size_t)it * 65536 + (size_t)(r0 + xr0 + rr) * 64 + 2 * lane;
        if (isK) *(u64*)&g_ks[g] = ln_pair(pair, lnd_p, 1.0f);
        else     *(u64*)&g_vl[g] = pair;
    }
}

// ======================= K3b: per-head q-chain + attention, one kernel ====
// 64 blocks (one per (b,h)); 3 internal iterations. Wlq staged once
// (transposed, conflict-free LDS.128); qcur in smem; ks/vl[it] prefetched
// via cp.async during the q-GEMV. Warp w owns e-rows {w, w+8}.
__global__ __launch_bounds__(256, 1) void k_QAtt(
    const float* __restrict__ Wlq, const float* __restrict__ blq,
    const float* __restrict__ lnc, const float* __restrict__ temp_p) {
    __shared__ u64 wl[2048];          // wl[s*64+j]
    __shared__ u64 sx[16 * 33];       // qcur
    __shared__ u64 sq[16 * 33];       // LN'd qs
    __shared__ u64 sk[16 * 33];       // ks[it]
    __shared__ u64 sv[16 * 33];       // vl[it]
    __shared__ float red[8];
    int tid = threadIdx.x, lane = tid & 31, w = tid >> 5;
    int bb = blockIdx.x >> 4, h = blockIdx.x & 15;
    for (int i = tid; i < 2048; i += 256) {
        int j = i >> 5, s = i & 31;
        cp8(smem_u32p(&wl[s * 64 + j]), &Wlq[j * 64 + 2 * s]);
    }
    for (int i = tid; i < 512; i += 256) {
        int e = i >> 5, s = i & 31;
        cp8(smem_u32p(&sx[e * 33 + s]),
            &g_q[((size_t)((bb * 16 + e) * 16 + h)) * 64 + 2 * s]);
    }
    cp_commit();
    u64 blq_p = *(const u64*)&blq[2 * lane];
    u64 lnc_p = *(const u64*)&lnc[2 * lane];
    float temp0 = temp_p[0];
    int e0 = w, e1 = w + 8;
    int f = lane & 15, dh = lane >> 4;
    u64 ap0 = 0, ap1 = 0;
    cp_wait0();
    __syncthreads();

    for (int it = 0; it < 3; it++) {
        // prefetch this iteration's ks/vl while doing the q-GEMV
        for (int i = tid; i < 512; i += 256) {
            int e = i >> 5, s = i & 31;
            size_t g = (size_t)it * 65536 +
                       ((size_t)((bb * 16 + e) * 16 + h)) * 64 + 2 * s;
            cp8(smem_u32p(&sk[e * 33 + s]), &g_ks[g]);
            cp8(smem_u32p(&sv[e * 33 + s]), &g_vl[g]);
        }
        cp_commit();

        // ---- q-GEMV: rows e0,e1, conflict-free weight LDS.128 ----
        u64 a00 = 0, a01 = 0, a10 = 0, a11 = 0;
#pragma unroll 8
        for (int s = 0; s < 32; s++) {
            ulonglong2 wv = *(const ulonglong2*)&wl[s * 64 + 2 * lane];
            u64 x0 = sx[e0 * 33 + s];
            u64 x1 = sx[e1 * 33 + s];
            ffma2(a00, x0, wv.x); ffma2(a01, x0, wv.y);
            ffma2(a10, x1, wv.x); ffma2(a11, x1, wv.y);
        }
        u64 ql0 = pack2(lo32(a00) + hi32(a00) + lo32(blq_p),
                        lo32(a01) + hi32(a01) + hi32(blq_p));
        u64 ql1 = pack2(lo32(a10) + hi32(a10) + lo32(blq_p),
                        lo32(a11) + hi32(a11) + hi32(blq_p));
        float t_it = temp0 + 0.005f * (float)it;
        float tsc = ((t_it != 1.0f) && (t_it > 0.f)) ? rsqrtf(t_it) : 1.0f;
        float sc = tsc * SM_SCALE;
        sq[e0 * 33 + lane] = ln_pair(ql0, lnc_p, sc);
        sq[e1 * 33 + lane] = ln_pair(ql1, lnc_p, sc);
        cp_wait0();
        __syncthreads();              // qs published, ks/vl arrived

        // ---- logits (rows e0,e1 vs col f, d-half dh) ----
        u64 acc0 = 0, acc1 = 0;
#pragma unroll
        for (int s = 0; s < 16; s++) {
            int p = dh * 16 + s;
            u64 kv = sk[f * 33 + p];
            ffma2(acc0, sq[e0 * 33 + p], kv);
            ffma2(acc1, sq[e1 * 33 + p], kv);
        }
        float lg0 = lo32(acc0) + hi32(acc0);
        float lg1 = lo32(acc1) + hi32(acc1);
        lg0 += __shfl_xor_sync(0xffffffffu, lg0, 16);
        lg1 += __shfl_xor_sync(0xffffffffu, lg1, 16);
        float mx0 = lg0, mx1 = lg1;
#pragma unroll
        for (int o = 8; o > 0; o >>= 1) {
            mx0 = fmaxf(mx0, __shfl_xor_sync(0xffffffffu, mx0, o, 16));
            mx1 = fmaxf(mx1, __shfl_xor_sync(0xffffffffu, mx1, o, 16));
        }
        float ex0 = __expf(lg0 - mx0), ex1 = __expf(lg1 - mx1);
        float s0 = ex0, s1 = ex1;
#pragma unroll
        for (int o = 8; o > 0; o >>= 1) {
            s0 += __shfl_xor_sync(0xffffffffu, s0, o, 16);
            s1 += __shfl_xor_sync(0xffffffffu, s1, o, 16);
        }
        float pr0 = __fdividef(ex0, s0), pr1 = __fdividef(ex1, s1);

        // ---- ai = softmax @ vl ----
        u64 av0 = 0, av1 = 0;
#pragma unroll
        for (int s = 0; s < 16; s++) {
            float p0 = __shfl_sync(0xffffffffu, pr0, s);
            float p1 = __shfl_sync(0xffffffffu, pr1, s);
            u64 vv = sv[s * 33 + lane];
            ffma2(av0, pack2(p0, p0), vv);
            ffma2(av1, pack2(p1, p1), vv);
        }

        // ---- bookkeeping ----
        size_t g0 = ((size_t)((bb * 16 + e0) * 16 + h)) * 64 + 2 * lane;
        size_t g1 = ((size_t)((bb * 16 + e1) * 16 + h)) * 64 + 2 * lane;
        if (it == 0) { ap0 = av0; ap1 = av1; }
        if (it == 1) {
            *(u64*)&g_ai1[g0] = av0;
            *(u64*)&g_ai1[g1] = av1;
            float ds = fabsf(lo32(av0) - lo32(ap0)) + fabsf(hi32(av0) - hi32(ap0))
                     + fabsf(lo32(av1) - lo32(ap1)) + fabsf(hi32(av1) - hi32(ap1));
            float tot = blockReduce256(ds, red);
            if (tid == 0) atomicAdd(&g_diffsum, tot);
        } else if (it == 2) {
            *(u64*)&g_ai2[g0] = av0;
            *(u64*)&g_ai2[g1] = av1;
        }
        if (it < 2) {   // qcur += ai (warp-private rows in smem)
            sx[e0 * 33 + lane] = fadd2(sx[e0 * 33 + lane], av0);
            sx[e1 * 33 + lane] = fadd2(sx[e1 * 33 + lane], av1);
        }
        __syncthreads();              // sq/sk/sv reads done before next iter
    }
}

// ======================= K4: select ai, Wo proj, red.v4 into out ==========
__global__ __launch_bounds__(128) void k_out(
    const float* __restrict__ Wo, const float* __restrict__ thrp,
    const float* __restrict__ facp, float* __restrict__ out) {
    extern __shared__ float sh[];
    float* sA = sh;
    float* sW = sh + 64 * TK;
    float diff1 = g_diffsum * (1.0f / 8388608.0f);  // mean over B*H*T*hd
    const float* A = (diff1 < thrp[0] + facp[0] * diff1) ? g_ai1 : g_ai2;
    int j0 = blockIdx.x * 128;
    int kb = blockIdx.y * TK;
    u64 acc[64] = {};
    stage_tile(A, Wo, j0, kb, sA, sW);
    cp_wait0();
    __syncthreads();
    int tid = threadIdx.x, rg = tid & 7, cg = tid >> 3;
    compute_tile(sA, sW, acc, rg, cg);
    int c0 = j0 + cg * 8;
#pragma unroll
    for (int i = 0; i < 8; i++) {
        int row = rg * 8 + i;
        int b = row >> 4, t = row & 15;
        float v[8];
#pragma unroll
        for (int j = 0; j < 8; j++) {
            float2 f = *(float2*)&acc[i * 8 + j];
            v[j] = f.x + f.y;
        }
        float* p = &out[((size_t)(b * Tn + t)) * Dn + c0];
        red4(p, v[0], v[1], v[2], v[3]);
        red4(p + 4, v[4], v[5], v[6], v[7]);
    }
}

// ======================= launch ===========================================
extern "C" void kernel_launch(void* const* d_in, const int* in_sizes, int n_in,
                              void* d_out, int out_size) {
    (void)in_sizes; (void)n_in; (void)out_size;
    const float* x    = (const float*)d_in[0];
    const float* Wq   = (const float*)d_in[1];
    const float* bq   = (const float*)d_in[2];
    const float* Wk   = (const float*)d_in[3];
    const float* Wv   = (const float*)d_in[4];
    const float* bv   = (const float*)d_in[5];
    const float* Wo   = (const float*)d_in[6];
    const float* bo   = (const float*)d_in[7];
    const float* lna  = (const float*)d_in[8];
    const float* lnc  = (const float*)d_in[9];
    const float* lnd  = (const float*)d_in[10];
    const float* Wlq  = (const float*)d_in[11];
    const float* blq  = (const float*)d_in[12];
    const float* Wlk  = (const float*)d_in[13];
    const float* blk  = (const float*)d_in[14];
    const float* Wlv  = (const float*)d_in[15];
    const float* blv  = (const float*)d_in[16];
    const float* temp = (const float*)d_in[17];
    const float* thr  = (const float*)d_in[18];
    const float* fac  = (const float*)d_in[19];
    float* out = (float*)d_out;

    static cudaStream_t s2 = nullptr;
    static cudaEvent_t evF = nullptr, evJ = nullptr, evP = nullptr;
    static bool attrs_set = false;
    if (s2 == nullptr) {
        cudaStreamCreateWithFlags(&s2, cudaStreamNonBlocking);
        cudaEventCreateWithFlags(&evF, cudaEventDisableTiming);
        cudaEventCreateWithFlags(&evJ, cudaEventDisableTiming);
        cudaEventCreateWithFlags(&evP, cudaEventDisableTiming);
    }
    if (!attrs_set) {
        cudaFuncSetAttribute(k_qkv, cudaFuncAttributeMaxDynamicSharedMemorySize, GEMM_SMEM);
        cudaFuncSetAttribute(k_out, cudaFuncAttributeMaxDynamicSharedMemorySize, GEMM_SMEM);
        attrs_set = true;
    }

    // fork: weight powers + bo-fill run concurrently on s2
    cudaEventRecord(evF, 0);
    cudaStreamWaitEvent(s2, evF, 0);
    k_pow<<<2, 256, 0, s2>>>(Wlk, blk, Wlv, blv);
    cudaEventRecord(evP, s2);
    k_fill<<<1024, 256, 0, s2>>>(bo, out);

    // main chain on stream 0
    k_ln<<<128, 256>>>(x, lna, bq, bv);
    k_qkv<<<dim3(8, 16, 3), 128, GEMM_SMEM>>>(Wq, Wk, Wv);
    cudaStreamWaitEvent(0, evP, 0);               // powers ready
    k_KV<<<dim3(32, 6), 256>>>(lnd);
    k_QAtt<<<64, 256>>>(Wlq, blq, lnc, temp);

    // join fill before final projection (which red.adds into out)
    cudaEventRecord(evJ, s2);
    cudaStreamWaitEvent(0, evJ, 0);
    k_out<<<dim3(8, 16), 128, GEMM_SMEM>>>(Wo, thr, fac, out);
}

// round 16
// speedup vs baseline: 1.4563x; 1.4563x over previous
#include <cuda_runtime.h>
#include <math.h>

#define Bn 4
#define Tn 2048
#define Dn 1024
#define Hn 16
#define HDn 64
#define En 16
#define Rn 64                     // Bn*En active rows
#define QK_SCALE 0.35355339059327373f   // hd^-0.25
#define SM_SCALE 0.125f                 // 1/sqrt(hd)

typedef unsigned long long u64;

// ---------------- scratch (static device globals; no allocation) ----------
__device__ float g_xn[Rn * Dn];
__device__ float g_q[Rn * Dn];     // q init (post-bias/scale), flat [1024][64]
__device__ float g_k[Rn * Dn];     // k init
__device__ float g_v[Rn * Dn];     // v init
__device__ float g_ks[3 * 65536];  // LN'd kl per iteration
__device__ float g_vl[3 * 65536];  // vl per iteration
__device__ float g_ai1[Rn * Dn];
__device__ float g_ai2[Rn * Dn];
__device__ float g_diffsum;

// ---------------- helpers -------------------------------------------------
__device__ __forceinline__ float warpReduceSum(float v) {
#pragma unroll
    for (int o = 16; o > 0; o >>= 1) v += __shfl_xor_sync(0xffffffffu, v, o);
    return v;
}

__device__ __forceinline__ float blockReduce256(float v, float* sh) {
    __syncthreads();
    v = warpReduceSum(v);
    int wid = threadIdx.x >> 5;
    if ((threadIdx.x & 31) == 0) sh[wid] = v;
    __syncthreads();
    if (threadIdx.x < 32) {
        float t = (threadIdx.x < 8) ? sh[threadIdx.x] : 0.f;
        t = warpReduceSum(t);
        if (threadIdx.x == 0) sh[0] = t;
    }
    __syncthreads();
    return sh[0];
}

// packed fp32x2 FMA (sm_100+)
__device__ __forceinline__ void ffma2(u64& d, u64 a, u64 b) {
    asm("fma.rn.f32x2 %0, %1, %2, %0;" : "+l"(d) : "l"(a), "l"(b));
}
__device__ __forceinline__ u64 fadd2(u64 a, u64 b) {
    u64 r;
    asm("add.rn.f32x2 %0, %1, %2;" : "=l"(r) : "l"(a), "l"(b));
    return r;
}
__device__ __forceinline__ u64 pack2(float a, float b) {
    u64 r;
    asm("mov.b64 %0, {%1, %2};" : "=l"(r) : "f"(a), "f"(b));
    return r;
}
__device__ __forceinline__ float lo32(u64 v) { return ((float2*)&v)->x; }
__device__ __forceinline__ float hi32(u64 v) { return ((float2*)&v)->y; }

__device__ __forceinline__ unsigned smem_u32p(const void* p) {
    return (unsigned)__cvta_generic_to_shared(p);
}
__device__ __forceinline__ void cp16(unsigned dst, const void* src) {
    asm volatile("cp.async.cg.shared.global [%0], [%1], 16;" :: "r"(dst), "l"(src));
}
__device__ __forceinline__ void cp8(unsigned dst, const void* src) {
    asm volatile("cp.async.ca.shared.global [%0], [%1], 8;" :: "r"(dst), "l"(src));
}
__device__ __forceinline__ void cp_commit() {
    asm volatile("cp.async.commit_group;");
}
__device__ __forceinline__ void cp_wait0() {
    asm volatile("cp.async.wait_group 0;");
}
__device__ __forceinline__ void cp_wait1() {
    asm volatile("cp.async.wait_group 1;");
}
// vector float atomic add (sm_90+)
__device__ __forceinline__ void red4(float* p, float a, float b, float c, float d) {
    asm volatile("red.global.add.v4.f32 [%0], {%1,%2,%3,%4};"
                 :: "l"(p), "f"(a), "f"(b), "f"(c), "f"(d) : "memory");
}

// full-warp LN over 64 elements held as one f32x2 pair per lane
__device__ __forceinline__ u64 ln_pair(u64 y, u64 gamma, float scale) {
    float a = lo32(y), b = hi32(y);
    float s = a + b;
#pragma unroll
    for (int o = 16; o > 0; o >>= 1) s += __shfl_xor_sync(0xffffffffu, s, o);
    float mean = s * (1.f / 64.f);
    float da = a - mean, db = b - mean;
    float q = da * da + db * db;
#pragma unroll
    for (int o = 16; o > 0; o >>= 1) q += __shfl_xor_sync(0xffffffffu, q, o);
    float inv = rsqrtf(q * (1.f / 64.f) + 1e-5f) * scale;
    return pack2(da * inv * lo32(gamma), db * inv * hi32(gamma));
}

// ======================= K1a: LN(64 rows) + accumulator inits =============
__global__ __launch_bounds__(256) void k_ln(
    const float* __restrict__ x, const float* __restrict__ lna,
    const float* __restrict__ bq, const float* __restrict__ bv) {
    if (blockIdx.x < Rn) {
        __shared__ float sh[8];
        if (blockIdx.x == 0 && threadIdx.x == 0) g_diffsum = 0.f;
        int r = blockIdx.x;
        int b = r >> 4, t = r & 15;
        const float* xr = x + ((size_t)(b * Tn + t)) * Dn;
        int tid = threadIdx.x;
        float v[4];
        float s = 0.f;
#pragma unroll
        for (int i = 0; i < 4; i++) { v[i] = xr[tid + i * 256]; s += v[i]; }
        s = blockReduce256(s, sh);
        float mean = s * (1.f / 1024.f);
        float sq = 0.f;
#pragma unroll
        for (int i = 0; i < 4; i++) { float d = v[i] - mean; sq += d * d; }
        sq = blockReduce256(sq, sh);
        float inv = rsqrtf(sq * (1.f / 1024.f) + 1e-5f);
#pragma unroll
        for (int i = 0; i < 4; i++) {
            int j = tid + i * 256;
            g_xn[r * Dn + j] = (v[i] - mean) * inv * lna[j];
        }
    } else {
        int r = blockIdx.x - Rn;
        int tid = threadIdx.x;
#pragma unroll
        for (int i = 0; i < 4; i++) {
            int j = tid + i * 256;
            g_q[r * Dn + j] = bq[j] * QK_SCALE;
            g_k[r * Dn + j] = 0.f;
            g_v[r * Dn + j] = bv[j];
        }
    }
}

// ======================= K1b: bo fill of whole output (side stream) =======
__global__ __launch_bounds__(256) void k_fill(
    const float* __restrict__ bo, float* __restrict__ out) {
    const float4* bo4 = (const float4*)bo;
    float4* o4 = (float4*)out;
    size_t total = (size_t)Bn * Tn * Dn / 4;
    size_t start = (size_t)blockIdx.x * 256 + threadIdx.x;
    size_t stride = (size_t)gridDim.x * 256;
    float4 v = bo4[start & 255];
    for (size_t i = start; i < total; i += stride) o4[i] = v;
}

// ======================= 64x128 FFMA2 GEMM tile core (split-wait) =========
#define TK 64

// stage k-half [half*32, half*32+32) of the A(64 rows) / W(128 rows) tile
__device__ __forceinline__ void stage_half(
    const float* __restrict__ A, const float* __restrict__ W,
    int j0, int kb, int half, float* sA, float* sW) {
    int tid = threadIdx.x;
    int kh = half * 32;
#pragma unroll
    for (int c = tid; c < 1024; c += 128) {       // A: 64 x 32 in 8B units
        int r = c >> 4;
        int kf = kh + (c & 15) * 2;
        int rg = r >> 3;
        int swz = ((rg & 3) * 8) | ((rg >> 2) * 2);   // bits<32: stays in half
        cp8(smem_u32p(&sA[r * TK + (kf ^ swz)]),
            &A[(size_t)r * Dn + kb + kf]);
    }
#pragma unroll
    for (int c = tid; c < 1024; c += 128) {       // W: 128 x 32 in 16B units
        int r = c >> 3;
        int kf = kh + (c & 7) * 4;
        cp16(smem_u32p(&sW[r * TK + kf]),
             &W[(size_t)(j0 + r) * Dn + kb + kf]);
    }
    cp_commit();
}

__device__ __forceinline__ void compute_half(
    const float* sA, const float* sW, u64* acc, int rg, int cg, int half) {
    int swz = ((rg & 3) * 8) | ((rg >> 2) * 2);
    const float* aBase = sA + rg * 8 * TK;
    const float* wBase = sW + cg * 8 * TK;
    int k0 = half * 32;
#pragma unroll 4
    for (int kk = k0; kk < k0 + 32; kk += 2) {
        int ka = kk ^ swz;
        u64 av[8], wv[8];
#pragma unroll
        for (int i = 0; i < 8; i++)
            av[i] = *(const u64*)&aBase[i * TK + ka];
#pragma unroll
        for (int j = 0; j < 8; j++)
            wv[j] = *(const u64*)&wBase[j * TK + kk];
#pragma unroll
        for (int i = 0; i < 8; i++)
#pragma unroll
            for (int j = 0; j < 8; j++) ffma2(acc[i * 8 + j], av[i], wv[j]);
    }
}
#define GEMM_SMEM ((64 + 128) * TK * 4)   // 49152 bytes

// ======================= K2: q,k,v GEMMs (k-split 16, red.v4) =============
// mbase selects which matrices this launch handles (m = mbase + blockIdx.z).
__global__ __launch_bounds__(128) void k_qkv(
    const float* __restrict__ Wq, const float* __restrict__ Wk,
    const float* __restrict__ Wv, int mbase) {
    extern __shared__ float sh[];
    float* sA = sh;
    float* sW = sh + 64 * TK;
    int m = mbase + blockIdx.z;
    const float* W = (m == 0) ? Wq : (m == 1) ? Wk : Wv;
    float* dst = (m == 0) ? g_q : (m == 1) ? g_k : g_v;
    float scale = (m == 2) ? 1.0f : QK_SCALE;
    int j0 = blockIdx.x * 128;
    int kb = blockIdx.y * TK;
    u64 acc[64] = {};
    stage_half(g_xn, W, j0, kb, 0, sA, sW);
    stage_half(g_xn, W, j0, kb, 1, sA, sW);
    int tid = threadIdx.x, rg = tid & 7, cg = tid >> 3;
    cp_wait1();                      // first half arrived
    __syncthreads();
    compute_half(sA, sW, acc, rg, cg, 0);
    cp_wait0();                      // second half arrived
    __syncthreads();
    compute_half(sA, sW, acc, rg, cg, 1);
    int c0 = j0 + cg * 8;
#pragma unroll
    for (int i = 0; i < 8; i++) {
        int row = rg * 8 + i;
        float v[8];
#pragma unroll
        for (int j = 0; j < 8; j++) {
            float2 f = *(float2*)&acc[i * 8 + j];
            v[j] = (f.x + f.y) * scale;
        }
        float* p = &dst[(size_t)row * Dn + c0];
        red4(p, v[0], v[1], v[2], v[3]);
        red4(p + 4, v[4], v[5], v[6], v[7]);
    }
}

// ======================= K3a: k/v recurrence (split K/V blocks) ===========
// grid 128: blocks 0..63 = K (rows bx*16..+15), 64..127 = V.
// Weights staged TRANSPOSED: wl[s*64 + j] = W[j][2s..2s+1], so each lane's
// (w0,w1) pair for cols (2l,2l+1) is ONE conflict-free LDS.128.
// 2 rows per warp; rows warp-private in smem -> __syncwarp only.
__global__ __launch_bounds__(256, 1) void k_KV(
    const float* __restrict__ Wlk, const float* __restrict__ blk,
    const float* __restrict__ Wlv, const float* __restrict__ blv,
    const float* __restrict__ lnd) {
    __shared__ u64 wl[2048];          // 16 KB, wl[s*64+j]
    __shared__ u64 sx[16 * 33];
    int tid = threadIdx.x, lane = tid & 31, w = tid >> 5;
    bool isK = (blockIdx.x < 64);
    int r0 = (isK ? blockIdx.x : blockIdx.x - 64) * 16;
    const float* Wm = isK ? Wlk : Wlv;
    const float* blp = isK ? blk : blv;
    const float* src = isK ? g_k : g_v;
    for (int i = tid; i < 2048; i += 256) {
        int j = i >> 5, s = i & 31;
        cp8(smem_u32p(&wl[s * 64 + j]), &Wm[j * 64 + 2 * s]);
    }
    for (int i = tid; i < 512; i += 256) {
        int r = i >> 5, s = i & 31;
        cp8(smem_u32p(&sx[r * 33 + s]), &src[(size_t)(r0 + r) * 64 + 2 * s]);
    }
    cp_commit();
    u64 bl_p = *(const u64*)&blp[2 * lane];
    u64 lnd_p = *(const u64*)&lnd[2 * lane];
    cp_wait0();
    __syncthreads();
    int xr0 = w * 2;

    for (int it = 0; it < 3; it++) {
        u64 acc[2][2] = {};
#pragma unroll 4
        for (int s = 0; s < 32; s++) {
            ulonglong2 wv = *(const ulonglong2*)&wl[s * 64 + 2 * lane];
            u64 x0 = sx[xr0 * 33 + s];
            u64 x1 = sx[(xr0 + 1) * 33 + s];
            ffma2(acc[0][0], x0, wv.x); ffma2(acc[0][1], x0, wv.y);
            ffma2(acc[1][0], x1, wv.x); ffma2(acc[1][1], x1, wv.y);
        }
        __syncwarp();                 // reads done before overwrite
#pragma unroll
        for (int rr = 0; rr < 2; rr++) {
            u64 pair = pack2(lo32(acc[rr][0]) + hi32(acc[rr][0]) + lo32(bl_p),
                             lo32(acc[rr][1]) + hi32(acc[rr][1]) + hi32(bl_p));
            sx[(xr0 + rr) * 33 + lane] = pair;
            size_t g = (size_t)it * 65536 + (size_t)(r0 + xr0 + rr) * 64 + 2 * lane;
            if (isK) *(u64*)&g_ks[g] = ln_pair(pair, lnd_p, 1.0f);
            else     *(u64*)&g_vl[g] = pair;
        }
        __syncwarp();                 // writes visible before next reads
    }
}

// ======================= K3b: per-head q-chain + attention, one kernel ====
// 64 blocks (one per (b,h)); 3 internal iterations. Wlq staged once
// (transposed, conflict-free LDS.128); qcur in smem; ks/vl[it] prefetched
// via cp.async during the q-GEMV. Warp w owns e-rows {w, w+8}.
__global__ __launch_bounds__(256, 1) void k_QAtt(
    const float* __restrict__ Wlq, const float* __restrict__ blq,
    const float* __restrict__ lnc, const float* __restrict__ temp_p) {
    __shared__ u64 wl[2048];          // wl[s*64+j]
    __shared__ u64 sx[16 * 33];       // qcur
    __shared__ u64 sq[16 * 33];       // LN'd qs
    __shared__ u64 sk[16 * 33];       // ks[it]
    __shared__ u64 sv[16 * 33];       // vl[it]
    __shared__ float red[8];
    int tid = threadIdx.x, lane = tid & 31, w = tid >> 5;
    int bb = blockIdx.x >> 4, h = blockIdx.x & 15;
    for (int i = tid; i < 2048; i += 256) {
        int j = i >> 5, s = i & 31;
        cp8(smem_u32p(&wl[s * 64 + j]), &Wlq[j * 64 + 2 * s]);
    }
    for (int i = tid; i < 512; i += 256) {
        int e = i >> 5, s = i & 31;
        cp8(smem_u32p(&sx[e * 33 + s]),
            &g_q[((size_t)((bb * 16 + e) * 16 + h)) * 64 + 2 * s]);
    }
    cp_commit();
    u64 blq_p = *(const u64*)&blq[2 * lane];
    u64 lnc_p = *(const u64*)&lnc[2 * lane];
    float temp0 = temp_p[0];
    int e0 = w, e1 = w + 8;
    int f = lane & 15, dh = lane >> 4;
    u64 ap0 = 0, ap1 = 0;
    cp_wait0();
    __syncthreads();

    for (int it = 0; it < 3; it++) {
        // prefetch this iteration's ks/vl while doing the q-GEMV
        for (int i = tid; i < 512; i += 256) {
            int e = i >> 5, s = i & 31;
            size_t g = (size_t)it * 65536 +
                       ((size_t)((bb * 16 + e) * 16 + h)) * 64 + 2 * s;
            cp8(smem_u32p(&sk[e * 33 + s]), &g_ks[g]);
            cp8(smem_u32p(&sv[e * 33 + s]), &g_vl[g]);
        }
        cp_commit();

        // ---- q-GEMV: rows e0,e1, conflict-free weight LDS.128 ----
        u64 a00 = 0, a01 = 0, a10 = 0, a11 = 0;
#pragma unroll 8
        for (int s = 0; s < 32; s++) {
            ulonglong2 wv = *(const ulonglong2*)&wl[s * 64 + 2 * lane];
            u64 x0 = sx[e0 * 33 + s];
            u64 x1 = sx[e1 * 33 + s];
            ffma2(a00, x0, wv.x); ffma2(a01, x0, wv.y);
            ffma2(a10, x1, wv.x); ffma2(a11, x1, wv.y);
        }
        u64 ql0 = pack2(lo32(a00) + hi32(a00) + lo32(blq_p),
                        lo32(a01) + hi32(a01) + hi32(blq_p));
        u64 ql1 = pack2(lo32(a10) + hi32(a10) + lo32(blq_p),
                        lo32(a11) + hi32(a11) + hi32(blq_p));
        float t_it = temp0 + 0.005f * (float)it;
        float tsc = ((t_it != 1.0f) && (t_it > 0.f)) ? rsqrtf(t_it) : 1.0f;
        float sc = tsc * SM_SCALE;
        sq[e0 * 33 + lane] = ln_pair(ql0, lnc_p, sc);
        sq[e1 * 33 + lane] = ln_pair(ql1, lnc_p, sc);
        cp_wait0();
        __syncthreads();              // qs published, ks/vl arrived

        // ---- logits (rows e0,e1 vs col f, d-half dh) ----
        u64 acc0 = 0, acc1 = 0;
#pragma unroll
        for (int s = 0; s < 16; s++) {
            int p = dh * 16 + s;
            u64 kv = sk[f * 33 + p];
            ffma2(acc0, sq[e0 * 33 + p], kv);
            ffma2(acc1, sq[e1 * 33 + p], kv);
        }
        float lg0 = lo32(acc0) + hi32(acc0);
        float lg1 = lo32(acc1) + hi32(acc1);
        lg0 += __shfl_xor_sync(0xffffffffu, lg0, 16);
        lg1 += __shfl_xor_sync(0xffffffffu, lg1, 16);
        float mx0 = lg0, mx1 = lg1;
#pragma unroll
        for (int o = 8; o > 0; o >>= 1) {
            mx0 = fmaxf(mx0, __shfl_xor_sync(0xffffffffu, mx0, o, 16));
            mx1 = fmaxf(mx1, __shfl_xor_sync(0xffffffffu, mx1, o, 16));
        }
        float ex0 = __expf(lg0 - mx0), ex1 = __expf(lg1 - mx1);
        float s0 = ex0, s1 = ex1;
#pragma unroll
        for (int o = 8; o > 0; o >>= 1) {
            s0 += __shfl_xor_sync(0xffffffffu, s0, o, 16);
            s1 += __shfl_xor_sync(0xffffffffu, s1, o, 16);
        }
        float pr0 = __fdividef(ex0, s0), pr1 = __fdividef(ex1, s1);

        // ---- ai = softmax @ vl ----
        u64 av0 = 0, av1 = 0;
#pragma unroll
        for (int s = 0; s < 16; s++) {
            float p0 = __shfl_sync(0xffffffffu, pr0, s);
            float p1 = __shfl_sync(0xffffffffu, pr1, s);
            u64 vv = sv[s * 33 + lane];
            ffma2(av0, pack2(p0, p0), vv);
            ffma2(av1, pack2(p1, p1), vv);
        }

        // ---- bookkeeping ----
        size_t g0 = ((size_t)((bb * 16 + e0) * 16 + h)) * 64 + 2 * lane;
        size_t g1 = ((size_t)((bb * 16 + e1) * 16 + h)) * 64 + 2 * lane;
        if (it == 0) { ap0 = av0; ap1 = av1; }
        if (it == 1) {
            *(u64*)&g_ai1[g0] = av0;
            *(u64*)&g_ai1[g1] = av1;
            float ds = fabsf(lo32(av0) - lo32(ap0)) + fabsf(hi32(av0) - hi32(ap0))
                     + fabsf(lo32(av1) - lo32(ap1)) + fabsf(hi32(av1) - hi32(ap1));
            float tot = blockReduce256(ds, red);
            if (tid == 0) atomicAdd(&g_diffsum, tot);
        } else if (it == 2) {
            *(u64*)&g_ai2[g0] = av0;
            *(u64*)&g_ai2[g1] = av1;
        }
        if (it < 2) {   // qcur += ai (warp-private rows in smem)
            sx[e0 * 33 + lane] = fadd2(sx[e0 * 33 + lane], av0);
            sx[e1 * 33 + lane] = fadd2(sx[e1 * 33 + lane], av1);
        }
        __syncthreads();              // sq/sk/sv reads done before next iter
    }
}

// ======================= K4: select ai, Wo proj, red.v4 into out ==========
__global__ __launch_bounds__(128) void k_out(
    const float* __restrict__ Wo, const float* __restrict__ thrp,
    const float* __restrict__ facp, float* __restrict__ out) {
    extern __shared__ float sh[];
    float* sA = sh;
    float* sW = sh + 64 * TK;
    float diff1 = g_diffsum * (1.0f / 8388608.0f);  // mean over B*H*T*hd
    const float* A = (diff1 < thrp[0] + facp[0] * diff1) ? g_ai1 : g_ai2;
    int j0 = blockIdx.x * 128;
    int kb = blockIdx.y * TK;
    u64 acc[64] = {};
    stage_half(A, Wo, j0, kb, 0, sA, sW);
    stage_half(A, Wo, j0, kb, 1, sA, sW);
    int tid = threadIdx.x, rg = tid & 7, cg = tid >> 3;
    cp_wait1();
    __syncthreads();
    compute_half(sA, sW, acc, rg, cg, 0);
    cp_wait0();
    __syncthreads();
    compute_half(sA, sW, acc, rg, cg, 1);
    int c0 = j0 + cg * 8;
#pragma unroll
    for (int i = 0; i < 8; i++) {
        int row = rg * 8 + i;
        int b = row >> 4, t = row & 15;
        float v[8];
#pragma unroll
        for (int j = 0; j < 8; j++) {
            float2 f = *(float2*)&acc[i * 8 + j];
            v[j] = f.x + f.y;
        }
        float* p = &out[((size_t)(b * Tn + t)) * Dn + c0];
        red4(p, v[0], v[1], v[2], v[3]);
        red4(p + 4, v[4], v[5], v[6], v[7]);
    }
}

// ======================= launch ===========================================
extern "C" void kernel_launch(void* const* d_in, const int* in_sizes, int n_in,
                              void* d_out, int out_size) {
    (void)in_sizes; (void)n_in; (void)out_size;
    const float* x    = (const float*)d_in[0];
    const float* Wq   = (const float*)d_in[1];
    const float* bq   = (const float*)d_in[2];
    const float* Wk   = (const float*)d_in[3];
    const float* Wv   = (const float*)d_in[4];
    const float* bv   = (const float*)d_in[5];
    const float* Wo   = (const float*)d_in[6];
    const float* bo   = (const float*)d_in[7];
    const float* lna  = (const float*)d_in[8];
    const float* lnc  = (const float*)d_in[9];
    const float* lnd  = (const float*)d_in[10];
    const float* Wlq  = (const float*)d_in[11];
    const float* blq  = (const float*)d_in[12];
    const float* Wlk  = (const float*)d_in[13];
    const float* blk  = (const float*)d_in[14];
    const float* Wlv  = (const float*)d_in[15];
    const float* blv  = (const float*)d_in[16];
    const float* temp = (const float*)d_in[17];
    const float* thr  = (const float*)d_in[18];
    const float* fac  = (const float*)d_in[19];
    float* out = (float*)d_out;

    static cudaStream_t s2 = nullptr;
    static cudaEvent_t evL = nullptr, evQ = nullptr, evJ = nullptr;
    static bool attrs_set = false;
    if (s2 == nullptr) {
        cudaStreamCreateWithFlags(&s2, cudaStreamNonBlocking);
        cudaEventCreateWithFlags(&evL, cudaEventDisableTiming);
        cudaEventCreateWithFlags(&evQ, cudaEventDisableTiming);
        cudaEventCreateWithFlags(&evJ, cudaEventDisableTiming);
    }
    if (!attrs_set) {
        cudaFuncSetAttribute(k_qkv, cudaFuncAttributeMaxDynamicSharedMemorySize, GEMM_SMEM);
        cudaFuncSetAttribute(k_out, cudaFuncAttributeMaxDynamicSharedMemorySize, GEMM_SMEM);
        attrs_set = true;
    }

    // main chain on stream 0: LN first
    k_ln<<<128, 256>>>(x, lna, bq, bv);
    cudaEventRecord(evL, 0);

    // side stream: q projection (needed only by k_QAtt) + bo fill
    cudaStreamWaitEvent(s2, evL, 0);
    k_qkv<<<dim3(8, 16, 1), 128, GEMM_SMEM, s2>>>(Wq, Wk, Wv, 0);   // q
    cudaEventRecord(evQ, s2);
    k_fill<<<1024, 256, 0, s2>>>(bo, out);
    cudaEventRecord(evJ, s2);

    // main chain: k,v projections -> kv recurrence -> q attention
    k_qkv<<<dim3(8, 16, 2), 128, GEMM_SMEM>>>(Wq, Wk, Wv, 1);       // k,v
    k_KV<<<128, 256>>>(Wlk, blk, Wlv, blv, lnd);
    cudaStreamWaitEvent(0, evQ, 0);               // q ready
    k_QAtt<<<64, 256>>>(Wlq, blq, lnc, temp);

    // join fill before final projection (which red.adds into out)
    cudaStreamWaitEvent(0, evJ, 0);
    k_out<<<dim3(8, 16), 128, GEMM_SMEM>>>(Wo, thr, fac, out);
}